// round 1
// baseline (speedup 1.0000x reference)
#include <cuda_runtime.h>

#define NB_ 64
#define NF_ 8
#define ED_ 64
#define ZSTRIDE 68      // floats per (n,f) row: conflict-free padding
#define NROWS 512       // NB_*NF_
#define NTHREADS 512

// smem layout (floats):
//  zs  : NROWS*ZSTRIDE = 34816
//  us  : NF_*ZSTRIDE   = 544
//  xs  : NF_*ZSTRIDE   = 544
//  pb  : 512
//  rz  : 512
//  red : 4*NF_*ZSTRIDE = 2176
//  sr  : 16
#define SMEM_FLOATS (NROWS*ZSTRIDE + 2*NF_*ZSTRIDE + 512 + 512 + 4*NF_*ZSTRIDE + 16)

__global__ __launch_bounds__(NTHREADS, 1)
void hete_attention_kernel(const float* __restrict__ feat,
                           const float* __restrict__ meta,
                           float* __restrict__ out)
{
    extern __shared__ float smem[];
    float* zs  = smem;                          // [512][68] raw z
    float* us  = zs + NROWS * ZSTRIDE;          // [8][68]
    float* xs  = us + NF_ * ZSTRIDE;            // [8][68]
    float* pb  = xs + NF_ * ZSTRIDE;            // [512] p_eff
    float* rz  = pb + 512;                      // [512] 1/||z_row||
    float* red = rz + 512;                      // [4][8][68] partials
    float* sr  = red + 4 * NF_ * ZSTRIDE;       // [16]

    const int b = blockIdx.x;
    const int t = threadIdx.x;
    const int lane = t & 31;
    const int w = t >> 5;

    // ---- Stage z (coalesced LDG.128 -> conflict-free STS.128) ----
    const float4* g4 = (const float4*)(meta + (size_t)b * (NB_ * NF_ * ED_));
    #pragma unroll
    for (int i = 0; i < 16; i++) {
        int idx4 = i * 512 + t;                 // 8192 float4 total
        float4 v = g4[idx4];
        int row = idx4 >> 4;                    // (n*8+f)
        int q   = idx4 & 15;                    // float4 within row
        *(float4*)(zs + row * ZSTRIDE + q * 4) = v;
    }

    // ---- x: load + L2-normalize per facet (warps 0..7, one per facet) ----
    if (w < NF_) {
        float2 v = *(const float2*)(feat + (size_t)b * 512 + w * 64 + lane * 2);
        float s = v.x * v.x + v.y * v.y;
        #pragma unroll
        for (int o = 16; o; o >>= 1) s += __shfl_xor_sync(0xffffffffu, s, o);
        float r = 1.0f / fmaxf(sqrtf(s), 1e-12f);
        float2 nv = make_float2(v.x * r, v.y * r);
        *(float2*)(xs + w * ZSTRIDE + lane * 2) = nv;
        *(float2*)(us + w * ZSTRIDE + lane * 2) = nv;   // u0 = x_norm
    }
    __syncthreads();

    // ---- Row reciprocal norms for z (thread t owns row t) ----
    {
        const float4* zr = (const float4*)(zs + t * ZSTRIDE);
        float s = 0.f;
        #pragma unroll
        for (int i = 0; i < 16; i++) {
            float4 v = zr[i];
            s += v.x * v.x + v.y * v.y + v.z * v.z + v.w * v.w;
        }
        rz[t] = 1.0f / fmaxf(sqrtf(s), 1e-12f);
    }
    __syncthreads();

    const int f1 = t & 7;                        // facet for pass1
    const float4* zrow = (const float4*)(zs + t * ZSTRIDE);
    const float4* urow = (const float4*)(us + f1 * ZSTRIDE);

    for (int it = 0; it < 3; it++) {
        // ---- Pass 1: logits + softmax over facets (8-lane groups) ----
        float acc = 0.f;
        #pragma unroll
        for (int i = 0; i < 16; i++) {
            float4 zv = zrow[i];
            float4 uv = urow[i];
            acc += zv.x * uv.x + zv.y * uv.y + zv.z * uv.z + zv.w * uv.w;
        }
        float rzt = rz[t];
        float logit = acc * rzt;
        float m = logit;
        m = fmaxf(m, __shfl_xor_sync(0xffffffffu, m, 1));
        m = fmaxf(m, __shfl_xor_sync(0xffffffffu, m, 2));
        m = fmaxf(m, __shfl_xor_sync(0xffffffffu, m, 4));
        float e = __expf(logit - m);
        float ssum = e;
        ssum += __shfl_xor_sync(0xffffffffu, ssum, 1);
        ssum += __shfl_xor_sync(0xffffffffu, ssum, 2);
        ssum += __shfl_xor_sync(0xffffffffu, ssum, 4);
        pb[t] = (e / ssum) * rzt;               // fold z-row norm into weight
        __syncthreads();

        // ---- Pass 2: partial u[f,d] = sum_n z*p over 16-n groups ----
        {
            int grp = t >> 7;                   // 0..3
            int rem = t & 127;
            int f   = rem >> 4;                 // 0..7
            int dq  = rem & 15;                 // float4 index in d
            float4 a = make_float4(0.f, 0.f, 0.f, 0.f);
            int n0 = grp * 16;
            #pragma unroll
            for (int k = 0; k < 16; k++) {
                int r = (n0 + k) * 8 + f;
                float4 zv = *(const float4*)(zs + r * ZSTRIDE + dq * 4);
                float pw = pb[r];
                a.x += zv.x * pw; a.y += zv.y * pw;
                a.z += zv.z * pw; a.w += zv.w * pw;
            }
            *(float4*)(red + (grp * 8 + f) * ZSTRIDE + dq * 4) = a;
        }
        __syncthreads();

        // ---- Pass 2b: combine partials, +x, (norm | store) ----
        {
            int f = t >> 6, d = t & 63;
            float v = red[(f)      * ZSTRIDE + d]
                    + red[(8 + f)  * ZSTRIDE + d]
                    + red[(16 + f) * ZSTRIDE + d]
                    + red[(24 + f) * ZSTRIDE + d]
                    + xs[f * ZSTRIDE + d];
            if (it < 2) {
                float s = v * v;
                #pragma unroll
                for (int o = 16; o; o >>= 1) s += __shfl_xor_sync(0xffffffffu, s, o);
                if (lane == 0) sr[w] = s;
                __syncthreads();
                float tot = sr[2 * f] + sr[2 * f + 1];
                float r = 1.0f / fmaxf(sqrtf(tot), 1e-12f);
                us[f * ZSTRIDE + d] = v * r;
                __syncthreads();
            } else {
                out[(size_t)b * 512 + t] = v;   // t == f*64+d
            }
        }
    }
}

extern "C" void kernel_launch(void* const* d_in, const int* in_sizes, int n_in,
                              void* d_out, int out_size)
{
    const float* feat = (const float*)d_in[0];   // [2048, 512]
    const float* meta = (const float*)d_in[1];   // [2048, 64, 512]
    float* out = (float*)d_out;

    const int B = in_sizes[0] / (NF_ * ED_);     // 2048
    const size_t smem_bytes = (size_t)SMEM_FLOATS * sizeof(float);

    cudaFuncSetAttribute(hete_attention_kernel,
                         cudaFuncAttributeMaxDynamicSharedMemorySize,
                         (int)smem_bytes);

    hete_attention_kernel<<<B, NTHREADS, smem_bytes>>>(feat, meta, out);
}

// round 2
// speedup vs baseline: 1.4321x; 1.4321x over previous
#include <cuda_runtime.h>
#include <cuda_fp16.h>

#define NB_ 64
#define NF_ 8
#define ED_ 64
#define NTHREADS 512
#define ZH 72        // halves per z row (64 data + 8 pad) = 144 B -> bank step 4 words/row
#define USTRIDE 68   // floats per u/x row
#define PSTRIDE 66   // floats per lg/pb/rz facet row (bank step 2 -> strided f-reads conflict-free)

// smem (floats): zs 18432 | us 544 | xs 544 | lg 528 | pb 528 | rzs 528 | red 4096 | sr 16
#define SMEM_FLOATS (18432 + 544 + 544 + 528 + 528 + 528 + 4096 + 16)

__device__ __forceinline__ void h8_to_f(uint4 zv, float2& a, float2& b, float2& c, float2& d) {
    a = __half22float2(*(const __half2*)&zv.x);
    b = __half22float2(*(const __half2*)&zv.y);
    c = __half22float2(*(const __half2*)&zv.z);
    d = __half22float2(*(const __half2*)&zv.w);
}

__global__ __launch_bounds__(NTHREADS, 2)
void hete_attention_kernel(const float* __restrict__ feat,
                           const float* __restrict__ meta,
                           float* __restrict__ out)
{
    extern __shared__ float smem[];
    __half* zs  = (__half*)smem;            // [8*64 rows][72 halves], f-major rows
    float* us   = smem + 18432;             // [8][68]
    float* xs   = us + NF_ * USTRIDE;       // [8][68]
    float* lg   = xs + NF_ * USTRIDE;       // [8][66] logits
    float* pb   = lg + NF_ * PSTRIDE;       // [8][66] p_eff = softmax * rz
    float* rzs  = pb + NF_ * PSTRIDE;       // [8][66] 1/||z_row||
    float* red  = rzs + NF_ * PSTRIDE;      // [8 grp][8 f][64 d]
    float* sr   = red + 4096;               // [16]

    const int b = blockIdx.x;
    const int t = threadIdx.x;
    const int lane = t & 31;
    const int w = t >> 5;

    // ---- x: load + L2-normalize per facet (warps 0..7) ----
    if (w < NF_) {
        float2 v = *(const float2*)(feat + (size_t)b * 512 + w * 64 + lane * 2);
        float s = v.x * v.x + v.y * v.y;
        #pragma unroll
        for (int o = 16; o; o >>= 1) s += __shfl_xor_sync(0xffffffffu, s, o);
        float r = 1.0f / fmaxf(sqrtf(s), 1e-12f);
        float2 nv = make_float2(v.x * r, v.y * r);
        *(float2*)(xs + w * USTRIDE + lane * 2) = nv;
        *(float2*)(us + w * USTRIDE + lane * 2) = nv;
    }

    // ---- Stage z: coalesced LDG.128 -> fp16, f-major rows ----
    const float4* g4 = (const float4*)(meta + (size_t)b * 32768);
    #pragma unroll 8
    for (int i = 0; i < 16; i++) {
        int idx4 = i * 512 + t;             // global float4 idx: n=idx4>>7, f=(idx4>>4)&7, q=idx4&15
        float4 v = g4[idx4];
        int n = idx4 >> 7;
        int f = (idx4 >> 4) & 7;
        int q = idx4 & 15;
        __half2 hh[2];
        hh[0] = __floats2half2_rn(v.x, v.y);
        hh[1] = __floats2half2_rn(v.z, v.w);
        *(uint2*)(zs + (f * 64 + n) * ZH + q * 4) = *(uint2*)hh;
    }
    __syncthreads();

    // ---- Per-row reciprocal norms (thread t owns f-major row t) ----
    float myrz;
    {
        const uint4* zr = (const uint4*)(zs + t * ZH);
        float s = 0.f;
        #pragma unroll
        for (int c = 0; c < 8; c++) {
            float2 a, bb, cc, dd; h8_to_f(zr[c], a, bb, cc, dd);
            s += a.x*a.x + a.y*a.y + bb.x*bb.x + bb.y*bb.y
               + cc.x*cc.x + cc.y*cc.y + dd.x*dd.x + dd.y*dd.y;
        }
        myrz = 1.0f / fmaxf(sqrtf(s), 1e-12f);
        rzs[(t >> 6) * PSTRIDE + (t & 63)] = myrz;
    }
    __syncthreads();

    const int f1 = t >> 6;                   // pass-1 facet: whole warp shares f -> u broadcast
    const int n1 = t & 63;
    const uint4* zrow = (const uint4*)(zs + t * ZH);
    const float* urow = us + f1 * USTRIDE;

    // pass-2 constants
    const int g2 = t >> 6, f2 = (t >> 3) & 7, c2 = t & 7;
    const __half* zb2 = zs + (f2 * 64 + g2 * 8) * ZH + c2 * 8;
    const float* pbase = pb + f2 * PSTRIDE + g2 * 8;

    for (int it = 0; it < 3; it++) {
        // ---- Pass 1: logit[f,n] = (z_row . u_f) * rz ----
        float acc = 0.f;
        #pragma unroll
        for (int c = 0; c < 8; c++) {
            float2 a, bb, cc, dd; h8_to_f(zrow[c], a, bb, cc, dd);
            float4 ua = *(const float4*)(urow + c * 8);
            float4 ub = *(const float4*)(urow + c * 8 + 4);
            acc += a.x*ua.x + a.y*ua.y + bb.x*ua.z + bb.y*ua.w
                 + cc.x*ub.x + cc.y*ub.y + dd.x*ub.z + dd.y*ub.w;
        }
        float logit = acc * myrz;
        lg[f1 * PSTRIDE + n1] = logit;
        __syncthreads();

        // ---- Softmax over facets (each thread redundantly for its n) ----
        {
            float mx = -1e30f;
            #pragma unroll
            for (int ff = 0; ff < 8; ff++) mx = fmaxf(mx, lg[ff * PSTRIDE + n1]);
            float ssum = 0.f;
            #pragma unroll
            for (int ff = 0; ff < 8; ff++) ssum += __expf(lg[ff * PSTRIDE + n1] - mx);
            pb[f1 * PSTRIDE + n1] = (__expf(logit - mx) / ssum) * myrz;
        }
        __syncthreads();

        // ---- Pass 2: partial u[f,d] over 8-n groups ----
        {
            float a0=0,a1=0,a2=0,a3=0,a4=0,a5=0,a6=0,a7=0;
            #pragma unroll
            for (int k = 0; k < 8; k++) {
                uint4 zv = *(const uint4*)(zb2 + k * ZH);
                float2 pa, pbq, pc, pd; h8_to_f(zv, pa, pbq, pc, pd);
                float pw = pbase[k];
                a0 += pa.x * pw;  a1 += pa.y * pw;
                a2 += pbq.x * pw; a3 += pbq.y * pw;
                a4 += pc.x * pw;  a5 += pc.y * pw;
                a6 += pd.x * pw;  a7 += pd.y * pw;
            }
            float* rdst = red + g2 * 512 + f2 * 64 + c2 * 8;
            *(float4*)(rdst)     = make_float4(a0, a1, a2, a3);
            *(float4*)(rdst + 4) = make_float4(a4, a5, a6, a7);
        }
        __syncthreads();

        // ---- Pass 2b: combine, +x, (norm | store) ----
        {
            int f = t >> 6, d = t & 63;
            float v = xs[f * USTRIDE + d];
            #pragma unroll
            for (int g = 0; g < 8; g++) v += red[g * 512 + f * 64 + d];
            if (it < 2) {
                float s = v * v;
                #pragma unroll
                for (int o = 16; o; o >>= 1) s += __shfl_xor_sync(0xffffffffu, s, o);
                if (lane == 0) sr[w] = s;
                __syncthreads();
                float tot = sr[2 * f] + sr[2 * f + 1];
                float r = 1.0f / fmaxf(sqrtf(tot), 1e-12f);
                us[f * USTRIDE + d] = v * r;
                __syncthreads();
            } else {
                out[(size_t)b * 512 + t] = v;   // t == f*64+d, matches output layout
            }
        }
    }
}

extern "C" void kernel_launch(void* const* d_in, const int* in_sizes, int n_in,
                              void* d_out, int out_size)
{
    const float* feat = (const float*)d_in[0];   // [2048, 512]
    const float* meta = (const float*)d_in[1];   // [2048, 64, 512]
    float* out = (float*)d_out;

    const int B = in_sizes[0] / (NF_ * ED_);     // 2048
    const size_t smem_bytes = (size_t)SMEM_FLOATS * sizeof(float);

    cudaFuncSetAttribute(hete_attention_kernel,
                         cudaFuncAttributeMaxDynamicSharedMemorySize,
                         (int)smem_bytes);

    hete_attention_kernel<<<B, NTHREADS, smem_bytes>>>(feat, meta, out);
}

// round 3
// speedup vs baseline: 1.4642x; 1.0224x over previous
#include <cuda_runtime.h>
#include <cuda_fp16.h>

#define NTHREADS 512
#define ZH 72            // halves per (f,n) z row (64 data + 8 pad)
#define FSTRIDE 4616     // halves per f-block: 64*ZH + 8  -> f-step = 4 banks
#define UH 72            // halves per u row
#define XSTR 68          // floats per x row
#define PSTR 68          // floats per pb row (bank = 4f+n, conflict-free)
#define RC 12            // floats per (g,f,c2) 8-d chunk (bank 12*c2 distinct)
#define RF 96            // 8*RC
#define RG 768           // 8*RF

// smem floats: zs 18464 | us_h 288 | xs 544 | pb 544 | red 6144 | sr 16
#define SMEM_FLOATS 26000

__global__ __launch_bounds__(NTHREADS, 2)
void hete_attention_kernel(const float* __restrict__ feat,
                           const float* __restrict__ meta,
                           float* __restrict__ out)
{
    extern __shared__ float smem[];
    __half* zs  = (__half*)smem;             // f-major: (f,n) row at f*FSTRIDE + n*ZH
    __half* us  = (__half*)(smem + 18464);   // [8][72] halves
    float*  xs  = smem + 18464 + 288;        // [8][68]
    float*  pb  = xs + 8 * XSTR;             // [8][68] p_eff fp32
    float*  red = pb + 8 * PSTR;             // [8 g][8 f][8 c][12]
    float*  sr  = red + 8 * RG;              // [16]

    const int b = blockIdx.x;
    const int t = threadIdx.x;
    const int lane = t & 31;
    const int w = t >> 5;

    // ---- x: load + L2-normalize per facet (warps 0..7); u0 = x_norm (fp16) ----
    if (w < 8) {
        float2 v = *(const float2*)(feat + (size_t)b * 512 + w * 64 + lane * 2);
        float s = v.x * v.x + v.y * v.y;
        #pragma unroll
        for (int o = 16; o; o >>= 1) s += __shfl_xor_sync(0xffffffffu, s, o);
        float r = 1.0f / fmaxf(sqrtf(s), 1e-12f);
        float2 nv = make_float2(v.x * r, v.y * r);
        *(float2*)(xs + w * XSTR + lane * 2) = nv;
        *(__half2*)(us + w * UH + lane * 2) = __floats2half2_rn(nv.x, nv.y);
    }

    // ---- Stage z: coalesced LDG.128 -> fp16 f-major ----
    const float4* g4 = (const float4*)(meta + (size_t)b * 32768);
    #pragma unroll
    for (int i = 0; i < 16; i++) {
        int idx4 = i * 512 + t;               // n=idx4>>7, f=(idx4>>4)&7, q=idx4&15
        float4 v = g4[idx4];
        int n = idx4 >> 7;
        int f = (idx4 >> 4) & 7;
        int q = idx4 & 15;
        __half2 hh[2];
        hh[0] = __floats2half2_rn(v.x, v.y);
        hh[1] = __floats2half2_rn(v.z, v.w);
        *(uint2*)(zs + f * FSTRIDE + n * ZH + q * 4) = *(uint2*)hh;
    }
    __syncthreads();

    const int f1 = t & 7;                      // pass-1: f in low lane bits -> shfl softmax
    const int n1 = t >> 3;
    const uint4* zrow4 = (const uint4*)(zs + f1 * FSTRIDE + n1 * ZH);
    const uint4* urow4 = (const uint4*)(us + f1 * UH);

    // ---- Row reciprocal norm (fp16 chains of 4, fp32 across chunks) ----
    float myrz;
    {
        float s = 0.f;
        #pragma unroll
        for (int c = 0; c < 8; c++) {
            uint4 zv = zrow4[c];
            const __half2* zh = (const __half2*)&zv;
            __half2 h = __hmul2(zh[0], zh[0]);
            h = __hfma2(zh[1], zh[1], h);
            h = __hfma2(zh[2], zh[2], h);
            h = __hfma2(zh[3], zh[3], h);
            float2 fx = __half22float2(h);
            s += fx.x + fx.y;
        }
        myrz = 1.0f / fmaxf(sqrtf(s), 1e-12f);
    }

    // pass-2 constants: g2 = n-group, f2 = facet, c2 = 8-d chunk
    const int g2 = t >> 6, f2 = (t >> 3) & 7, c2 = t & 7;
    const __half* zb2 = zs + f2 * FSTRIDE + (g2 * 8) * ZH + c2 * 8;
    const float* pbase = pb + f2 * PSTR + g2 * 8;

    for (int it = 0; it < 3; it++) {
        // ---- Pass 1: logit = (z_row . u_f) * rz via HFMA2 chains ----
        float acc = 0.f;
        #pragma unroll
        for (int c = 0; c < 8; c++) {
            uint4 zv = zrow4[c];
            uint4 uv = urow4[c];
            const __half2* zh = (const __half2*)&zv;
            const __half2* uh = (const __half2*)&uv;
            __half2 h = __hmul2(zh[0], uh[0]);
            h = __hfma2(zh[1], uh[1], h);
            h = __hfma2(zh[2], uh[2], h);
            h = __hfma2(zh[3], uh[3], h);
            float2 fx = __half22float2(h);
            acc += fx.x + fx.y;
        }
        float logit = acc * myrz;

        // ---- Softmax over facets: pure shuffles within 8-lane groups ----
        float m = logit;
        m = fmaxf(m, __shfl_xor_sync(0xffffffffu, m, 1));
        m = fmaxf(m, __shfl_xor_sync(0xffffffffu, m, 2));
        m = fmaxf(m, __shfl_xor_sync(0xffffffffu, m, 4));
        float e = __expf(logit - m);
        float ssum = e;
        ssum += __shfl_xor_sync(0xffffffffu, ssum, 1);
        ssum += __shfl_xor_sync(0xffffffffu, ssum, 2);
        ssum += __shfl_xor_sync(0xffffffffu, ssum, 4);
        pb[f1 * PSTR + n1] = (e / ssum) * myrz;
        __syncthreads();

        // ---- Pass 2: partial u[f, 8d] over 8-n group (fp32 accumulate) ----
        {
            float a0=0,a1=0,a2=0,a3=0,a4=0,a5=0,a6=0,a7=0;
            #pragma unroll
            for (int k = 0; k < 8; k++) {
                uint4 zv = *(const uint4*)(zb2 + k * ZH);
                const __half2* zh = (const __half2*)&zv;
                float2 pa = __half22float2(zh[0]);
                float2 pc = __half22float2(zh[1]);
                float2 pe = __half22float2(zh[2]);
                float2 pg = __half22float2(zh[3]);
                float pw = pbase[k];
                a0 += pa.x * pw; a1 += pa.y * pw;
                a2 += pc.x * pw; a3 += pc.y * pw;
                a4 += pe.x * pw; a5 += pe.y * pw;
                a6 += pg.x * pw; a7 += pg.y * pw;
            }
            float* rdst = red + g2 * RG + f2 * RF + c2 * RC;
            *(float4*)(rdst)     = make_float4(a0, a1, a2, a3);
            *(float4*)(rdst + 4) = make_float4(a4, a5, a6, a7);
        }
        __syncthreads();

        // ---- Pass 2b: combine partials, +x, (norm -> u fp16 | store) ----
        {
            int f = t >> 6, d = t & 63;
            float v = xs[f * XSTR + d];
            int roff = f * RF + (d >> 3) * RC + (d & 7);
            #pragma unroll
            for (int g = 0; g < 8; g++) v += red[g * RG + roff];
            if (it < 2) {
                float s = v * v;
                #pragma unroll
                for (int o = 16; o; o >>= 1) s += __shfl_xor_sync(0xffffffffu, s, o);
                if (lane == 0) sr[w] = s;
                __syncthreads();
                float tot = sr[2 * f] + sr[2 * f + 1];
                float r = 1.0f / fmaxf(sqrtf(tot), 1e-12f);
                us[f * UH + d] = __float2half(v * r);
                __syncthreads();
            } else {
                out[(size_t)b * 512 + t] = v;     // t == f*64+d
            }
        }
    }
}

extern "C" void kernel_launch(void* const* d_in, const int* in_sizes, int n_in,
                              void* d_out, int out_size)
{
    const float* feat = (const float*)d_in[0];   // [2048, 512]
    const float* meta = (const float*)d_in[1];   // [2048, 64, 512]
    float* out = (float*)d_out;

    const int B = in_sizes[0] / 512;             // 2048
    const size_t smem_bytes = (size_t)SMEM_FLOATS * sizeof(float);

    cudaFuncSetAttribute(hete_attention_kernel,
                         cudaFuncAttributeMaxDynamicSharedMemorySize,
                         (int)smem_bytes);

    hete_attention_kernel<<<B, NTHREADS, smem_bytes>>>(feat, meta, out);
}

// round 4
// speedup vs baseline: 1.4983x; 1.0233x over previous
#include <cuda_runtime.h>
#include <cuda_fp16.h>

#define NTHREADS 512
#define ZH 72            // halves per (f,n) z row (64 data + 8 pad)
#define FSTRIDE 4616     // halves per f-block: 64*ZH + 8  -> f-step = 4 banks
#define UH 72            // halves per u row
#define XSTR 68          // floats per x row
#define PSTR 68          // floats per pb row
#define RC 12            // floats per (g,f,c) 8-d chunk
#define RF 96            // 8*RC
#define RG 768           // 8*RF

// smem floats: zs 18464 | us_h 288 | xs 544 | pb 544 | red 6144
#define SMEM_FLOATS (18464 + 288 + 544 + 544 + 6144)

__device__ __forceinline__ float dot_h2x4(const __half2* a, const __half2* b) {
    __half2 h = __hmul2(a[0], b[0]);
    h = __hfma2(a[1], b[1], h);
    h = __hfma2(a[2], b[2], h);
    h = __hfma2(a[3], b[3], h);
    float2 fx = __half22float2(h);
    return fx.x + fx.y;
}

__global__ __launch_bounds__(NTHREADS, 2)
void hete_attention_kernel(const float* __restrict__ feat,
                           const float* __restrict__ meta,
                           float* __restrict__ out)
{
    extern __shared__ float smem[];
    __half* zs  = (__half*)smem;             // f-major: (f,n) row at f*FSTRIDE + n*ZH
    __half* us  = (__half*)(smem + 18464);   // [8][72] halves
    float*  xs  = smem + 18464 + 288;        // [8][68]
    float*  pb  = xs + 8 * XSTR;             // [8][68] p_eff fp32
    float*  red = pb + 8 * PSTR;             // [8 g][8 f][8 c][12]

    const int b = blockIdx.x;
    const int t = threadIdx.x;
    const int lane = t & 31;
    const int w = t >> 5;

    // ---- x: load + L2-normalize per facet (warps 0..7); u0 = x_norm (fp16) ----
    if (w < 8) {
        float2 v = *(const float2*)(feat + (size_t)b * 512 + w * 64 + lane * 2);
        float s = v.x * v.x + v.y * v.y;
        #pragma unroll
        for (int o = 16; o; o >>= 1) s += __shfl_xor_sync(0xffffffffu, s, o);
        float r = 1.0f / fmaxf(sqrtf(s), 1e-12f);
        float2 nv = make_float2(v.x * r, v.y * r);
        *(float2*)(xs + w * XSTR + lane * 2) = nv;
        *(__half2*)(us + w * UH + lane * 2) = __floats2half2_rn(nv.x, nv.y);
    }

    // ---- Stage z: coalesced LDG.128 -> fp16 f-major ----
    const float4* g4 = (const float4*)(meta + (size_t)b * 32768);
    #pragma unroll
    for (int i = 0; i < 16; i++) {
        int idx4 = i * 512 + t;               // n=idx4>>7, f=(idx4>>4)&7, q=idx4&15
        float4 v = g4[idx4];
        int n = idx4 >> 7;
        int f = (idx4 >> 4) & 7;
        int q = idx4 & 15;
        __half2 hh[2];
        hh[0] = __floats2half2_rn(v.x, v.y);
        hh[1] = __floats2half2_rn(v.z, v.w);
        *(uint2*)(zs + f * FSTRIDE + n * ZH + q * 4) = *(uint2*)hh;
    }
    __syncthreads();

    // ---- Pass-1 thread constants: warp g1 owns 4 n; c1 = 16-d chunk; f1 facet ----
    const int f1 = t & 7;
    const int c1 = (t >> 3) & 3;
    const int g1 = t >> 5;                    // == warp id
    const uint4* zc = (const uint4*)(zs + f1 * FSTRIDE + (g1 * 4) * ZH + c1 * 16);
    const uint4* uc = (const uint4*)(us + f1 * UH + c1 * 16);

    // ---- rz for the warp's 4 rows (chunk self-dot + c-reduce), kept in regs ----
    float rzv[4];
    #pragma unroll
    for (int j = 0; j < 4; j++) {
        uint4 zr[2] = { zc[j * 9], zc[j * 9 + 1] };
        const __half2* zh = (const __half2*)zr;
        float s = dot_h2x4(zh, zh) + dot_h2x4(zh + 4, zh + 4);
        s += __shfl_xor_sync(0xffffffffu, s, 8);
        s += __shfl_xor_sync(0xffffffffu, s, 16);
        rzv[j] = 1.0f / fmaxf(sqrtf(s), 1e-12f);
    }

    // ---- Pass-2 constants: g2 = 8-n group, f2 = facet, c2 = 8-d chunk ----
    const int g2 = t >> 6, f2 = (t >> 3) & 7, c2 = t & 7;
    const __half* zb2 = zs + f2 * FSTRIDE + (g2 * 8) * ZH + c2 * 8;
    const float* pbase = pb + f2 * PSTR + g2 * 8;

    for (int it = 0; it < 3; it++) {
        // ---- Pass 1: u loaded once per thread, reused over 4 n ----
        uint4 ur[2] = { uc[0], uc[1] };
        const __half2* uh = (const __half2*)ur;
        float dj[4];
        #pragma unroll
        for (int j = 0; j < 4; j++) {
            uint4 zr[2] = { zc[j * 9], zc[j * 9 + 1] };
            const __half2* zh = (const __half2*)zr;
            dj[j] = dot_h2x4(zh, uh) + dot_h2x4(zh + 4, uh + 4);
        }
        // reduce partial dots over the 4 d-chunks (lanes differing in bits 3,4)
        #pragma unroll
        for (int j = 0; j < 4; j++) {
            dj[j] += __shfl_xor_sync(0xffffffffu, dj[j], 8);
            dj[j] += __shfl_xor_sync(0xffffffffu, dj[j], 16);
        }
        // softmax over f (lanes 0..2 bits); logits bounded in [-1,1] -> no max needed
        #pragma unroll
        for (int j = 0; j < 4; j++) {
            float e = __expf(dj[j] * rzv[j]);
            float ssum = e;
            ssum += __shfl_xor_sync(0xffffffffu, ssum, 1);
            ssum += __shfl_xor_sync(0xffffffffu, ssum, 2);
            ssum += __shfl_xor_sync(0xffffffffu, ssum, 4);
            dj[j] = __fdividef(e, ssum) * rzv[j];     // p_eff
        }
        if (c1 == 0) {
            #pragma unroll
            for (int j = 0; j < 4; j++) pb[f1 * PSTR + g1 * 4 + j] = dj[j];
        }
        __syncthreads();

        // ---- Pass 2: partial u[f, 8d] over 8-n group (fp32 accumulate) ----
        {
            float a0=0,a1=0,a2=0,a3=0,a4=0,a5=0,a6=0,a7=0;
            #pragma unroll
            for (int k = 0; k < 8; k++) {
                uint4 zv = *(const uint4*)(zb2 + k * ZH);
                const __half2* zh = (const __half2*)&zv;
                float2 pa = __half22float2(zh[0]);
                float2 pc = __half22float2(zh[1]);
                float2 pe = __half22float2(zh[2]);
                float2 pg = __half22float2(zh[3]);
                float pw = pbase[k];
                a0 += pa.x * pw; a1 += pa.y * pw;
                a2 += pc.x * pw; a3 += pc.y * pw;
                a4 += pe.x * pw; a5 += pe.y * pw;
                a6 += pg.x * pw; a7 += pg.y * pw;
            }
            float* rdst = red + g2 * RG + f2 * RF + c2 * RC;
            *(float4*)(rdst)     = make_float4(a0, a1, a2, a3);
            *(float4*)(rdst + 4) = make_float4(a4, a5, a6, a7);
        }
        __syncthreads();

        // ---- Epilogue: warp w<8 owns facet f=w, 2 d per lane ----
        if (w < 8) {
            int d0 = lane * 2;
            float2 v = *(const float2*)(xs + w * XSTR + d0);
            int roff = w * RF + (d0 >> 3) * RC + (d0 & 7);
            #pragma unroll
            for (int g = 0; g < 8; g++) {
                float2 rv = *(const float2*)(red + g * RG + roff);
                v.x += rv.x; v.y += rv.y;
            }
            if (it < 2) {
                float s = v.x * v.x + v.y * v.y;
                #pragma unroll
                for (int o = 16; o; o >>= 1) s += __shfl_xor_sync(0xffffffffu, s, o);
                float r = 1.0f / fmaxf(sqrtf(s), 1e-12f);
                *(__half2*)(us + w * UH + d0) = __floats2half2_rn(v.x * r, v.y * r);
            } else {
                *(float2*)(out + (size_t)b * 512 + w * 64 + d0) = v;
            }
        }
        if (it < 2) __syncthreads();
    }
}

extern "C" void kernel_launch(void* const* d_in, const int* in_sizes, int n_in,
                              void* d_out, int out_size)
{
    const float* feat = (const float*)d_in[0];   // [2048, 512]
    const float* meta = (const float*)d_in[1];   // [2048, 64, 512]
    float* out = (float*)d_out;

    const int B = in_sizes[0] / 512;             // 2048
    const size_t smem_bytes = (size_t)SMEM_FLOATS * sizeof(float);

    cudaFuncSetAttribute(hete_attention_kernel,
                         cudaFuncAttributeMaxDynamicSharedMemorySize,
                         (int)smem_bytes);

    hete_attention_kernel<<<B, NTHREADS, smem_bytes>>>(feat, meta, out);
}

// round 5
// speedup vs baseline: 1.5547x; 1.0377x over previous
#include <cuda_runtime.h>
#include <cuda_fp16.h>

#define NTHREADS 512
#define UH 72              // halves per u row: LDS.128 banks 4f mod 32 distinct
#define XSTR 68            // floats per x row
#define PB_C 216           // halves per c-block of partial buffer (432 B, 16B-mult)
#define PB_G 864           // halves per g-block (4 c-blocks)
#define PB_HALVES (16 * PB_G)   // 13824 halves = 6912 floats

// smem floats: us 288 | xs 544 | part 6912
#define SMEM_FLOATS (288 + 544 + PB_HALVES / 2)

__global__ __launch_bounds__(NTHREADS, 2)
void hete_attention_kernel(const float* __restrict__ feat,
                           const float* __restrict__ meta,
                           float* __restrict__ out)
{
    extern __shared__ float smem[];
    __half* us   = (__half*)smem;             // [8][72] halves
    float*  xs   = smem + 288;                // [8][68]
    __half* part = (__half*)(smem + 288 + 544);

    const int b    = blockIdx.x;
    const int t    = threadIdx.x;
    const int lane = t & 31;
    const int w    = t >> 5;

    // thread z-ownership: f = lane 0-2, c = lane 3-4 (16-d chunk), g = warp (4 n)
    const int f = t & 7;
    const int c = (t >> 3) & 3;
    const int g = t >> 5;

    // ---- x: load + L2-normalize per facet (warps 0..7); u0 = x_norm (fp16) ----
    if (w < 8) {
        float2 v = *(const float2*)(feat + (size_t)b * 512 + w * 64 + lane * 2);
        float s = v.x * v.x + v.y * v.y;
        #pragma unroll
        for (int o = 16; o; o >>= 1) s += __shfl_xor_sync(0xffffffffu, s, o);
        float r = rsqrtf(fmaxf(s, 1e-24f));
        float2 nv = make_float2(v.x * r, v.y * r);
        *(float2*)(xs + w * XSTR + lane * 2) = nv;
        *(__half2*)(us + w * UH + lane * 2) = __floats2half2_rn(nv.x, nv.y);
    }

    // ---- z: HBM -> registers (fp16), 4 rows x 16 d per thread ----
    __half2 zr[4][8];
    {
        const float4* gz = (const float4*)(meta + (size_t)b * 32768);
        #pragma unroll
        for (int j = 0; j < 4; j++) {
            const float4* rp = gz + ((g * 4 + j) * 128 + f * 16 + c * 4);
            #pragma unroll
            for (int q = 0; q < 4; q++) {
                float4 v = rp[q];
                zr[j][q * 2]     = __floats2half2_rn(v.x, v.y);
                zr[j][q * 2 + 1] = __floats2half2_rn(v.z, v.w);
            }
        }
    }

    // ---- fold L2 norm into z: self-dot, reduce over c (lane bits 3,4), scale ----
    #pragma unroll
    for (int j = 0; j < 4; j++) {
        __half2 h = __hmul2(zr[j][0], zr[j][0]);
        #pragma unroll
        for (int k = 1; k < 8; k++) h = __hfma2(zr[j][k], zr[j][k], h);
        float2 fx = __half22float2(h);
        float s = fx.x + fx.y;
        s += __shfl_xor_sync(0xffffffffu, s, 8);
        s += __shfl_xor_sync(0xffffffffu, s, 16);
        float r = rsqrtf(fmaxf(s, 1e-24f));
        __half2 rh = __half2half2(__float2half(r));
        #pragma unroll
        for (int k = 0; k < 8; k++) zr[j][k] = __hmul2(zr[j][k], rh);
    }

    // pass-1 u pointer (2 uint4, conflict-free), partial-write pointer
    const uint4* ucp = (const uint4*)(us + f * UH + c * 16);
    __half* pwr = part + g * PB_G + c * PB_C + f * 24;

    // epilogue (warps 0..7): facet = w, d-pair = 2*lane
    const int d0 = lane * 2;
    const __half2* prd2 = (const __half2*)(part + (d0 >> 4) * PB_C + w * 24 + (d0 & 15));

    __syncthreads();

    for (int it = 0; it < 3; it++) {
        // ---- Pass 1: dot(z_row_norm, u_f) over 16 d, reduce over c, softmax over f ----
        uint4 u0 = ucp[0], u1 = ucp[1];
        __half2 uh[8];
        *(uint4*)(uh)     = u0;
        *(uint4*)(uh + 4) = u1;
        float dj[4];
        #pragma unroll
        for (int j = 0; j < 4; j++) {
            __half2 h = __hmul2(zr[j][0], uh[0]);
            #pragma unroll
            for (int k = 1; k < 8; k++) h = __hfma2(zr[j][k], uh[k], h);
            float2 fx = __half22float2(h);
            dj[j] = fx.x + fx.y;
        }
        #pragma unroll
        for (int j = 0; j < 4; j++) {
            dj[j] += __shfl_xor_sync(0xffffffffu, dj[j], 8);
            dj[j] += __shfl_xor_sync(0xffffffffu, dj[j], 16);
        }
        // logits are cosines in [-1,1]: exp safe without max-subtraction
        #pragma unroll
        for (int j = 0; j < 4; j++) {
            float e = __expf(dj[j]);
            float ssum = e;
            ssum += __shfl_xor_sync(0xffffffffu, ssum, 1);
            ssum += __shfl_xor_sync(0xffffffffu, ssum, 2);
            ssum += __shfl_xor_sync(0xffffffffu, ssum, 4);
            dj[j] = __fdividef(e, ssum);          // p (z-norm already folded into zr)
        }

        // ---- Pass 2: partial u[f,16d] over this thread's 4 n (fp16 accumulate) ----
        {
            __half2 acc[8];
            __half2 p0 = __half2half2(__float2half(dj[0]));
            #pragma unroll
            for (int k = 0; k < 8; k++) acc[k] = __hmul2(zr[0][k], p0);
            #pragma unroll
            for (int j = 1; j < 4; j++) {
                __half2 pj = __half2half2(__float2half(dj[j]));
                #pragma unroll
                for (int k = 0; k < 8; k++) acc[k] = __hfma2(zr[j][k], pj, acc[k]);
            }
            *(uint4*)(pwr)     = *(uint4*)(acc);
            *(uint4*)(pwr + 8) = *(uint4*)(acc + 4);
        }
        __syncthreads();

        // ---- Epilogue: warp w<8 owns facet w, 2 d per lane; 16-way g reduce ----
        if (w < 8) {
            float2 v = *(const float2*)(xs + w * XSTR + d0);
            #pragma unroll
            for (int gg = 0; gg < 16; gg++) {
                float2 pv = __half22float2(prd2[gg * (PB_G / 2)]);
                v.x += pv.x; v.y += pv.y;
            }
            if (it < 2) {
                float s = v.x * v.x + v.y * v.y;
                #pragma unroll
                for (int o = 16; o; o >>= 1) s += __shfl_xor_sync(0xffffffffu, s, o);
                float r = rsqrtf(fmaxf(s, 1e-24f));
                *(__half2*)(us + w * UH + d0) = __floats2half2_rn(v.x * r, v.y * r);
            } else {
                *(float2*)(out + (size_t)b * 512 + w * 64 + d0) = v;
            }
        }
        if (it < 2) __syncthreads();
    }
}

extern "C" void kernel_launch(void* const* d_in, const int* in_sizes, int n_in,
                              void* d_out, int out_size)
{
    const float* feat = (const float*)d_in[0];   // [2048, 512]
    const float* meta = (const float*)d_in[1];   // [2048, 64, 512]
    float* out = (float*)d_out;

    const int B = in_sizes[0] / 512;             // 2048
    const size_t smem_bytes = (size_t)SMEM_FLOATS * sizeof(float);

    cudaFuncSetAttribute(hete_attention_kernel,
                         cudaFuncAttributeMaxDynamicSharedMemorySize,
                         (int)smem_bytes);

    hete_attention_kernel<<<B, NTHREADS, smem_bytes>>>(feat, meta, out);
}

// round 6
// speedup vs baseline: 1.9401x; 1.2478x over previous
#include <cuda_runtime.h>
#include <cuda_fp16.h>

#define NTHREADS 512
#define UH 72              // halves per u row
#define XSTR 68            // floats per x row
#define PGS 528            // halves per warp-group partial block (8*64 + 16 pad)

// smem floats: us 288 | xs 544 | part 16*528/2 = 4224
#define SMEM_FLOATS (288 + 544 + 16 * PGS / 2)

// Reduce-scatter 16 values over lane bits 0-3: returns, on lane with dq = lane&15,
// the full 16-lane sum of v[dq]. (kept-index bit == lane bit at each step)
__device__ __forceinline__ float reduce_scatter16(const float* v, int lane) {
    float a[8];
    {
        const bool hb = (lane & 8) != 0;
        #pragma unroll
        for (int k = 0; k < 8; k++) {
            float snd = hb ? v[k] : v[k + 8];
            float rcv = __shfl_xor_sync(0xffffffffu, snd, 8);
            a[k] = (hb ? v[k + 8] : v[k]) + rcv;
        }
    }
    float c[4];
    {
        const bool hb = (lane & 4) != 0;
        #pragma unroll
        for (int k = 0; k < 4; k++) {
            float snd = hb ? a[k] : a[k + 4];
            float rcv = __shfl_xor_sync(0xffffffffu, snd, 4);
            c[k] = (hb ? a[k + 4] : a[k]) + rcv;
        }
    }
    float e[2];
    {
        const bool hb = (lane & 2) != 0;
        #pragma unroll
        for (int k = 0; k < 2; k++) {
            float snd = hb ? c[k] : c[k + 2];
            float rcv = __shfl_xor_sync(0xffffffffu, snd, 2);
            e[k] = (hb ? c[k + 2] : c[k]) + rcv;
        }
    }
    {
        const bool hb = (lane & 1) != 0;
        float snd = hb ? e[0] : e[1];
        float rcv = __shfl_xor_sync(0xffffffffu, snd, 1);
        return (hb ? e[1] : e[0]) + rcv;
    }
}

__global__ __launch_bounds__(NTHREADS, 2)
void hete_attention_kernel(const float* __restrict__ feat,
                           const float* __restrict__ meta,
                           float* __restrict__ out)
{
    extern __shared__ float smem[];
    __half* us   = (__half*)smem;              // [8][72] halves
    float*  xs   = smem + 288;                 // [8][68]
    __half* part = (__half*)(smem + 288 + 544);// [16 w][8 f][16 dq][4 d] + pad

    const int b    = blockIdx.x;
    const int t    = threadIdx.x;
    const int lane = t & 31;
    const int w    = t >> 5;
    const int hi   = lane >> 4;                // f parity
    const int dq   = lane & 15;                // d-quad (4 d)

    // ---- x: load + L2-normalize per facet (warps 0..7); u0 = x_norm (fp16) ----
    if (w < 8) {
        float2 v = *(const float2*)(feat + (size_t)b * 512 + w * 64 + lane * 2);
        float s = v.x * v.x + v.y * v.y;
        #pragma unroll
        for (int o = 16; o; o >>= 1) s += __shfl_xor_sync(0xffffffffu, s, o);
        float r = rsqrtf(fmaxf(s, 1e-24f));
        float2 nv = make_float2(v.x * r, v.y * r);
        *(float2*)(xs + w * XSTR + lane * 2) = nv;
        *(__half2*)(us + w * UH + lane * 2) = __floats2half2_rn(nv.x, nv.y);
    }

    // ---- z: fully coalesced HBM -> registers ----
    // thread i-th load owns: n = 4w + (i>>2), f = 2*(i&3) + hi, d = 4*dq..+3
    __half2 zr[32];
    {
        const float4* gz = (const float4*)(meta + (size_t)b * 32768) + w * 512 + lane;
        #pragma unroll
        for (int i = 0; i < 16; i++) {
            float4 v = gz[i * 32];
            zr[2 * i]     = __floats2half2_rn(v.x, v.y);
            zr[2 * i + 1] = __floats2half2_rn(v.z, v.w);
        }
    }

    // ---- fold row L2-norms into zr ----
    {
        float sd[16];
        #pragma unroll
        for (int i = 0; i < 16; i++) {
            __half2 h = __hmul2(zr[2 * i], zr[2 * i]);
            h = __hfma2(zr[2 * i + 1], zr[2 * i + 1], h);
            float2 fx = __half22float2(h);
            sd[i] = fx.x + fx.y;
        }
        float S = reduce_scatter16(sd, lane);      // row (j=dq>>2, m=dq&3)
        float r = rsqrtf(fmaxf(S, 1e-24f));
        #pragma unroll
        for (int k = 0; k < 16; k++) {
            float rk = __shfl_sync(0xffffffffu, r, (lane & 16) | k);
            __half2 rh = __half2half2(__float2half(rk));
            zr[2 * k]     = __hmul2(zr[2 * k], rh);
            zr[2 * k + 1] = __hmul2(zr[2 * k + 1], rh);
        }
    }

    __half* pw = part + w * PGS + dq * 4;          // + f*64 per m at store time

    __syncthreads();

    for (int it = 0; it < 3; it++) {
        // ---- u load: 4 facets (2m+hi), own d-quad ----
        __half2 uh[8];
        #pragma unroll
        for (int m = 0; m < 4; m++)
            *(uint2*)&uh[2 * m] = *(const uint2*)(us + (2 * m + hi) * UH + dq * 4);

        // ---- partial dots over own 4 d for all 16 (n,f) rows ----
        float dj[16];
        #pragma unroll
        for (int i = 0; i < 16; i++) {
            __half2 h = __hmul2(zr[2 * i], uh[2 * (i & 3)]);
            h = __hfma2(zr[2 * i + 1], uh[2 * (i & 3) + 1], h);
            float2 fx = __half22float2(h);
            dj[i] = fx.x + fx.y;
        }

        // ---- scatter-reduce -> one logit per lane; softmax over f ----
        float L = reduce_scatter16(dj, lane);      // (n = 4w + (dq>>2), f = 2*(dq&3)+hi)
        float e = __expf(L);                       // cosines in [-1,1]: no max needed
        float s = e;
        s += __shfl_xor_sync(0xffffffffu, s, 1);   // sum over m bit0
        s += __shfl_xor_sync(0xffffffffu, s, 2);   // sum over m bit1
        s += __shfl_xor_sync(0xffffffffu, s, 16);  // other f parity
        float p = __fdividef(e, s);

        // ---- allgather p for this thread's 16 rows (same parity hi) ----
        float pg[16];
        #pragma unroll
        for (int k = 0; k < 16; k++)
            pg[k] = __shfl_sync(0xffffffffu, p, (lane & 16) | k);

        // ---- pass 2: acc[f=2m+hi][4 d] over 4 n (fp16 accumulate) ----
        __half2 acc[8];
        #pragma unroll
        for (int m = 0; m < 4; m++) {
            __half2 ph = __half2half2(__float2half(pg[m]));
            acc[2 * m]     = __hmul2(zr[2 * m], ph);
            acc[2 * m + 1] = __hmul2(zr[2 * m + 1], ph);
        }
        #pragma unroll
        for (int j = 1; j < 4; j++) {
            #pragma unroll
            for (int m = 0; m < 4; m++) {
                int i = 4 * j + m;
                __half2 ph = __half2half2(__float2half(pg[i]));
                acc[2 * m]     = __hfma2(zr[2 * i], ph, acc[2 * m]);
                acc[2 * m + 1] = __hfma2(zr[2 * i + 1], ph, acc[2 * m + 1]);
            }
        }
        #pragma unroll
        for (int m = 0; m < 4; m++)
            *(uint2*)(pw + (2 * m + hi) * 64) = *(uint2*)&acc[2 * m];
        __syncthreads();

        // ---- epilogue: warp f<8 combines 16 warp-partials, +x, norm|store ----
        if (w < 8) {
            int d0 = lane * 2;
            float2 v = *(const float2*)(xs + w * XSTR + d0);
            #pragma unroll
            for (int g = 0; g < 16; g++) {
                __half2 hv = ((const __half2*)(part + g * PGS + w * 64))[lane];
                float2 fv = __half22float2(hv);
                v.x += fv.x; v.y += fv.y;
            }
            if (it < 2) {
                float s2 = v.x * v.x + v.y * v.y;
                #pragma unroll
                for (int o = 16; o; o >>= 1) s2 += __shfl_xor_sync(0xffffffffu, s2, o);
                float r = rsqrtf(fmaxf(s2, 1e-24f));
                *(__half2*)(us + w * UH + d0) = __floats2half2_rn(v.x * r, v.y * r);
            } else {
                *(float2*)(out + (size_t)b * 512 + w * 64 + d0) = v;
            }
        }
        if (it < 2) __syncthreads();
    }
}

extern "C" void kernel_launch(void* const* d_in, const int* in_sizes, int n_in,
                              void* d_out, int out_size)
{
    const float* feat = (const float*)d_in[0];   // [2048, 512]
    const float* meta = (const float*)d_in[1];   // [2048, 64, 512]
    float* out = (float*)d_out;

    const int B = in_sizes[0] / 512;             // 2048
    const size_t smem_bytes = (size_t)SMEM_FLOATS * sizeof(float);

    cudaFuncSetAttribute(hete_attention_kernel,
                         cudaFuncAttributeMaxDynamicSharedMemorySize,
                         (int)smem_bytes);

    hete_attention_kernel<<<B, NTHREADS, smem_bytes>>>(feat, meta, out);
}

// round 7
// speedup vs baseline: 2.3153x; 1.1934x over previous
#include <cuda_runtime.h>
#include <cuda_fp16.h>

#define NTHREADS 512
#define UH 72              // halves per u row
#define XSTR 68            // floats per x row
#define PGS 528            // halves per warp-group partial block (8*64 + 16 pad)

// smem floats: us 288 | xs 544 | part 16*528/2 = 4224
#define SMEM_FLOATS (288 + 544 + 16 * PGS / 2)

// Reduce-scatter 16 values over lane bits 0-3: returns, on lane with dq = lane&15,
// the full 16-lane sum of v[dq].
__device__ __forceinline__ float reduce_scatter16(const float* v, int lane) {
    float a[8];
    {
        const bool hb = (lane & 8) != 0;
        #pragma unroll
        for (int k = 0; k < 8; k++) {
            float snd = hb ? v[k] : v[k + 8];
            float rcv = __shfl_xor_sync(0xffffffffu, snd, 8);
            a[k] = (hb ? v[k + 8] : v[k]) + rcv;
        }
    }
    float c[4];
    {
        const bool hb = (lane & 4) != 0;
        #pragma unroll
        for (int k = 0; k < 4; k++) {
            float snd = hb ? a[k] : a[k + 4];
            float rcv = __shfl_xor_sync(0xffffffffu, snd, 4);
            c[k] = (hb ? a[k + 4] : a[k]) + rcv;
        }
    }
    float e[2];
    {
        const bool hb = (lane & 2) != 0;
        #pragma unroll
        for (int k = 0; k < 2; k++) {
            float snd = hb ? c[k] : c[k + 2];
            float rcv = __shfl_xor_sync(0xffffffffu, snd, 2);
            e[k] = (hb ? c[k + 2] : c[k]) + rcv;
        }
    }
    {
        const bool hb = (lane & 1) != 0;
        float snd = hb ? e[0] : e[1];
        float rcv = __shfl_xor_sync(0xffffffffu, snd, 1);
        return (hb ? e[1] : e[0]) + rcv;
    }
}

__global__ __launch_bounds__(NTHREADS, 2)
void hete_attention_kernel(const float* __restrict__ feat,
                           const float* __restrict__ meta,
                           float* __restrict__ out)
{
    extern __shared__ float smem[];
    __half* us   = (__half*)smem;              // [8][72] halves
    float*  xs   = smem + 288;                 // [8][68]
    __half* part = (__half*)(smem + 288 + 544);// [16 w][8 f][16 dq][4 d] + pad

    const int b    = blockIdx.x;
    const int t    = threadIdx.x;
    const int lane = t & 31;
    const int w    = t >> 5;
    const int hi   = lane >> 4;                // f parity
    const int dq   = lane & 15;                // d-quad (4 d)

    // ---- x: load + L2-normalize per facet (warps 0..7); u0 = x_norm (fp16) ----
    if (w < 8) {
        float2 v = *(const float2*)(feat + (size_t)b * 512 + w * 64 + lane * 2);
        float s = v.x * v.x + v.y * v.y;
        #pragma unroll
        for (int o = 16; o; o >>= 1) s += __shfl_xor_sync(0xffffffffu, s, o);
        float r = rsqrtf(fmaxf(s, 1e-24f));
        float2 nv = make_float2(v.x * r, v.y * r);
        *(float2*)(xs + w * XSTR + lane * 2) = nv;
        *(__half2*)(us + w * UH + lane * 2) = __floats2half2_rn(nv.x, nv.y);
    }

    // ---- z: fully coalesced HBM -> registers (raw fp16, norms NOT folded) ----
    // load i owns: n = 4w + (i>>2), f = 2*(i&3) + hi, d = 4*dq..+3
    __half2 zr[32];
    {
        const float4* gz = (const float4*)(meta + (size_t)b * 32768) + w * 512 + lane;
        #pragma unroll
        for (int i = 0; i < 16; i++) {
            float4 v = gz[i * 32];
            zr[2 * i]     = __floats2half2_rn(v.x, v.y);
            zr[2 * i + 1] = __floats2half2_rn(v.z, v.w);
        }
    }

    // ---- row reciprocal norm: lane holds rzv for row (n=4w+(dq>>2), f=2*(dq&3)+hi) ----
    float rzv;
    {
        float sd[16];
        #pragma unroll
        for (int i = 0; i < 16; i++) {
            __half2 h = __hmul2(zr[2 * i], zr[2 * i]);
            h = __hfma2(zr[2 * i + 1], zr[2 * i + 1], h);
            float2 fx = __half22float2(h);
            sd[i] = fx.x + fx.y;
        }
        float S = reduce_scatter16(sd, lane);
        rzv = rsqrtf(fmaxf(S, 1e-24f));
    }

    __half* pwp = part + w * PGS + dq * 4;         // + f*64 per m at store time

    __syncthreads();

    for (int it = 0; it < 3; it++) {
        // ---- u load: 4 facets (2m+hi), own d-quad ----
        __half2 uh[8];
        #pragma unroll
        for (int m = 0; m < 4; m++)
            *(uint2*)&uh[2 * m] = *(const uint2*)(us + (2 * m + hi) * UH + dq * 4);

        // ---- partial raw dots over own 4 d for all 16 (n,f) rows ----
        float dj[16];
        #pragma unroll
        for (int i = 0; i < 16; i++) {
            __half2 h = __hmul2(zr[2 * i], uh[2 * (i & 3)]);
            h = __hfma2(zr[2 * i + 1], uh[2 * (i & 3) + 1], h);
            float2 fx = __half22float2(h);
            dj[i] = fx.x + fx.y;
        }

        // ---- scatter-reduce -> logit (x rz); softmax over f ----
        float L = reduce_scatter16(dj, lane) * rzv;
        float e = __expf(L);                       // cosines in [-1,1]: no max needed
        float s = e;
        s += __shfl_xor_sync(0xffffffffu, s, 1);   // sum over m bit0
        s += __shfl_xor_sync(0xffffffffu, s, 2);   // sum over m bit1
        s += __shfl_xor_sync(0xffffffffu, s, 16);  // other f parity
        float p_eff = __fdividef(e, s) * rzv;      // z-row norm folded into weight

        // ---- packed fp16 allgather: pair with lane^8, then 8 half2 gathers ----
        __half ph = __float2half(p_eff);
        unsigned pv = (unsigned)__half_as_ushort(ph);
        unsigned po = __shfl_xor_sync(0xffffffffu, pv, 8);
        __half2 P2 = __halves2half2(ph, __ushort_as_half((unsigned short)po));
        unsigned P2u = *(unsigned*)&P2;
        __half2 g[8];
        #pragma unroll
        for (int k = 0; k < 8; k++) {
            unsigned gu = __shfl_sync(0xffffffffu, P2u, (lane & 16) | k);
            g[k] = *(__half2*)&gu;                 // (p_eff[row k], p_eff[row k+8])
        }

        // ---- pass 2: acc[f=2m+hi][4 d] over 4 n (fp16 accumulate, raw z) ----
        __half2 acc[8];
        #pragma unroll
        for (int m = 0; m < 4; m++) {
            __half2 ph2 = __low2half2(g[m]);       // row i=m (<8)
            acc[2 * m]     = __hmul2(zr[2 * m], ph2);
            acc[2 * m + 1] = __hmul2(zr[2 * m + 1], ph2);
        }
        #pragma unroll
        for (int j = 1; j < 4; j++) {
            #pragma unroll
            for (int m = 0; m < 4; m++) {
                int i = 4 * j + m;
                __half2 ph2 = (i < 8) ? __low2half2(g[i]) : __high2half2(g[i - 8]);
                acc[2 * m]     = __hfma2(zr[2 * i], ph2, acc[2 * m]);
                acc[2 * m + 1] = __hfma2(zr[2 * i + 1], ph2, acc[2 * m + 1]);
            }
        }
        #pragma unroll
        for (int m = 0; m < 4; m++)
            *(uint2*)(pwp + (2 * m + hi) * 64) = *(uint2*)&acc[2 * m];
        __syncthreads();

        // ---- epilogue: warp f<8 combines 16 warp-partials (fp32), +x, norm|store ----
        if (w < 8) {
            int d0 = lane * 2;
            float2 v = *(const float2*)(xs + w * XSTR + d0);
            #pragma unroll
            for (int gg = 0; gg < 16; gg++) {
                __half2 hv = ((const __half2*)(part + gg * PGS + w * 64))[lane];
                float2 fv = __half22float2(hv);
                v.x += fv.x; v.y += fv.y;
            }
            if (it < 2) {
                float s2 = v.x * v.x + v.y * v.y;
                #pragma unroll
                for (int o = 16; o; o >>= 1) s2 += __shfl_xor_sync(0xffffffffu, s2, o);
                float r = rsqrtf(fmaxf(s2, 1e-24f));
                *(__half2*)(us + w * UH + d0) = __floats2half2_rn(v.x * r, v.y * r);
            } else {
                *(float2*)(out + (size_t)b * 512 + w * 64 + d0) = v;
            }
        }
        if (it < 2) __syncthreads();
    }
}

extern "C" void kernel_launch(void* const* d_in, const int* in_sizes, int n_in,
                              void* d_out, int out_size)
{
    const float* feat = (const float*)d_in[0];   // [2048, 512]
    const float* meta = (const float*)d_in[1];   // [2048, 64, 512]
    float* out = (float*)d_out;

    const int B = in_sizes[0] / 512;             // 2048
    const size_t smem_bytes = (size_t)SMEM_FLOATS * sizeof(float);

    cudaFuncSetAttribute(hete_attention_kernel,
                         cudaFuncAttributeMaxDynamicSharedMemorySize,
                         (int)smem_bytes);

    hete_attention_kernel<<<B, NTHREADS, smem_bytes>>>(feat, meta, out);
}

// round 8
// speedup vs baseline: 2.4044x; 1.0385x over previous
#include <cuda_runtime.h>
#include <cuda_fp16.h>

#define NTHREADS 512
#define UH 80              // halves per u row (f-step = 8 banks)
#define XSTR 68            // floats per x row
#define PFS 80             // halves per facet block in partial buffer
#define PWS 648            // halves per warp block (8*80 + 8 pad, 16B-mult)

// smem floats: us 320 | xs 544 | part 16*648/2 = 5184
#define SMEM_FLOATS (320 + 544 + 16 * PWS / 2)

// Reduce-scatter 8 values over lane bits 1-3: lane (b1,b2,b3) ends with the
// 8-lane-group sum of v[b1 + 2*b2 + 4*b3].
__device__ __forceinline__ float reduce_scatter8(const float* v, int lane) {
    float a[4];
    {
        const bool hb = (lane & 8) != 0;           // k-bit2
        #pragma unroll
        for (int k = 0; k < 4; k++) {
            float snd = hb ? v[k] : v[k + 4];
            float rcv = __shfl_xor_sync(0xffffffffu, snd, 8);
            a[k] = (hb ? v[k + 4] : v[k]) + rcv;
        }
    }
    float c[2];
    {
        const bool hb = (lane & 4) != 0;           // k-bit1
        #pragma unroll
        for (int k = 0; k < 2; k++) {
            float snd = hb ? a[k] : a[k + 2];
            float rcv = __shfl_xor_sync(0xffffffffu, snd, 4);
            c[k] = (hb ? a[k + 2] : a[k]) + rcv;
        }
    }
    {
        const bool hb = (lane & 2) != 0;           // k-bit0
        float snd = hb ? c[0] : c[1];
        float rcv = __shfl_xor_sync(0xffffffffu, snd, 2);
        return (hb ? c[1] : c[0]) + rcv;
    }
}

__global__ __launch_bounds__(NTHREADS, 2)
void hete_attention_kernel(const float* __restrict__ feat,
                           const float* __restrict__ meta,
                           float* __restrict__ out)
{
    extern __shared__ float smem[];
    __half* us   = (__half*)smem;              // [8][80] halves
    float*  xs   = smem + 320;                 // [8][68]
    __half* part = (__half*)(smem + 320 + 544);// [16 w][8 f][64 d] (+pad)

    const int b    = blockIdx.x;
    const int t    = threadIdx.x;
    const int lane = t & 31;
    const int w    = t >> 5;
    const int hi   = lane >> 4;                // f parity (bit4)
    const int po   = lane & 1;                 // pair parity (bit0)
    const int a    = (lane >> 1) & 7;          // 8-d chunk index

    // ---- x: load + L2-normalize per facet (warps 0..7); u0 = x_norm (fp16) ----
    if (w < 8) {
        float2 v = *(const float2*)(feat + (size_t)b * 512 + w * 64 + lane * 2);
        float s = v.x * v.x + v.y * v.y;
        #pragma unroll
        for (int o = 16; o; o >>= 1) s += __shfl_xor_sync(0xffffffffu, s, o);
        float r = rsqrtf(fmaxf(s, 1e-24f));
        float2 nv = make_float2(v.x * r, v.y * r);
        *(float2*)(xs + w * XSTR + lane * 2) = nv;
        *(__half2*)(us + w * UH + lane * 2) = __floats2half2_rn(nv.x, nv.y);
    }

    // ---- z: fully coalesced HBM -> fp16 registers ----
    // load i owns: n = 4w + (i>>2), f = 2*(i&3) + hi, d = 4*(lane&15)..+3
    __half2 zr[32];
    {
        const float4* gz = (const float4*)(meta + (size_t)b * 32768) + w * 512 + lane;
        #pragma unroll
        for (int i = 0; i < 16; i++) {
            float4 v = gz[i * 32];
            zr[2 * i]     = __floats2half2_rn(v.x, v.y);
            zr[2 * i + 1] = __floats2half2_rn(v.z, v.w);
        }
    }

    // ---- one-time lane-pair transpose: thread ends owning 8 rows x 8 d ----
    // row k = load-row (2k+po): j = k>>1, m = 2*(k&1)+po, f = 4*(k&1)+2*po+hi,
    // d = 8a..8a+7
    #pragma unroll
    for (int k = 0; k < 8; k++) {
        unsigned a0 = *(unsigned*)&zr[4 * k];
        unsigned a1 = *(unsigned*)&zr[4 * k + 1];
        unsigned b0 = *(unsigned*)&zr[4 * k + 2];
        unsigned b1 = *(unsigned*)&zr[4 * k + 3];
        unsigned s0 = po ? a0 : b0;
        unsigned s1 = po ? a1 : b1;
        unsigned r0 = __shfl_xor_sync(0xffffffffu, s0, 1);
        unsigned r1 = __shfl_xor_sync(0xffffffffu, s1, 1);
        unsigned o0 = po ? r0 : a0, o1 = po ? r1 : a1;
        unsigned o2 = po ? b0 : r0, o3 = po ? b1 : r1;
        zr[4 * k]     = *(__half2*)&o0;
        zr[4 * k + 1] = *(__half2*)&o1;
        zr[4 * k + 2] = *(__half2*)&o2;
        zr[4 * k + 3] = *(__half2*)&o3;
    }

    // ---- row reciprocal norms: scatter-reduce over the 8 d-chunk lanes ----
    float rzv;
    {
        float sd[8];
        #pragma unroll
        for (int k = 0; k < 8; k++) {
            __half2 h = __hmul2(zr[4 * k], zr[4 * k]);
            h = __hfma2(zr[4 * k + 1], zr[4 * k + 1], h);
            h = __hfma2(zr[4 * k + 2], zr[4 * k + 2], h);
            h = __hfma2(zr[4 * k + 3], zr[4 * k + 3], h);
            float2 fx = __half22float2(h);
            sd[k] = fx.x + fx.y;
        }
        float S = reduce_scatter8(sd, lane);
        rzv = rsqrtf(fmaxf(S, 1e-24f));
    }

    // facet ids for this thread's rows: even k -> fA, odd k -> fB
    const int fA = 2 * po + hi;
    const int fB = fA + 4;
    const __half* uA = us + fA * UH + a * 8;
    const __half* uB = us + fB * UH + a * 8;
    __half* pA = part + w * PWS + fA * PFS + a * 8;
    __half* pB = part + w * PWS + fB * PFS + a * 8;
    const int gidx = lane & 17;                  // base for p gather

    __syncthreads();

    for (int it = 0; it < 3; it++) {
        // ---- u chunks for the 2 facets (LDS.128, conflict-free) ----
        __half2 uhA[4], uhB[4];
        *(uint4*)uhA = *(const uint4*)uA;
        *(uint4*)uhB = *(const uint4*)uB;

        // ---- 8 row-dots over own 8 d ----
        float dj[8];
        #pragma unroll
        for (int k = 0; k < 8; k++) {
            const __half2* uu = (k & 1) ? uhB : uhA;
            __half2 h = __hmul2(zr[4 * k], uu[0]);
            h = __hfma2(zr[4 * k + 1], uu[1], h);
            h = __hfma2(zr[4 * k + 2], uu[2], h);
            h = __hfma2(zr[4 * k + 3], uu[3], h);
            float2 fx = __half22float2(h);
            dj[k] = fx.x + fx.y;
        }

        // ---- scatter-reduce -> logit; softmax over f (bits 1, 0->xor2/1? see map) ----
        // lane holds row (n = 4w + bits{2,3}, f = 4*bit1 + 2*bit0 + bit4)
        float L = reduce_scatter8(dj, lane) * rzv;
        float e = __expf(L);                       // cosines in [-1,1]
        float s = e;
        s += __shfl_xor_sync(0xffffffffu, s, 1);
        s += __shfl_xor_sync(0xffffffffu, s, 2);
        s += __shfl_xor_sync(0xffffffffu, s, 16);
        float p_eff = __fdividef(e, s) * rzv;

        // ---- packed fp16 gather of own 8 rows' p ----
        __half ph = __float2half(p_eff);
        unsigned pv = (unsigned)__half_as_ushort(ph);
        unsigned p8 = __shfl_xor_sync(0xffffffffu, pv, 8);
        __half2 P2 = __halves2half2(ph, __ushort_as_half((unsigned short)p8));
        unsigned P2u = *(unsigned*)&P2;
        __half2 g[4];
        #pragma unroll
        for (int k = 0; k < 4; k++) {
            unsigned gu = __shfl_sync(0xffffffffu, P2u, gidx | (k << 1));
            g[k] = *(__half2*)&gu;                 // (p row k, p row k+4)
        }

        // ---- pass 2: accA (even k, fA) and accB (odd k, fB), fp16 accumulate ----
        __half2 accA[4], accB[4];
        {
            __half2 ph0 = __low2half2(g[0]);       // row 0
            __half2 ph1 = __low2half2(g[1]);       // row 1 (wait: row1 -> ?)
            // row k mapping to g: k<4 -> low(g[k]); k>=4 -> high(g[k-4])
            #pragma unroll
            for (int r = 0; r < 4; r++) {
                accA[r] = __hmul2(zr[r], ph0);             // k=0
                accB[r] = __hmul2(zr[4 + r], ph1);         // k=1
            }
            #pragma unroll
            for (int k = 2; k < 8; k++) {
                __half2 pk = (k < 4) ? __low2half2(g[k]) : __high2half2(g[k - 4]);
                __half2* acc = (k & 1) ? accB : accA;
                #pragma unroll
                for (int r = 0; r < 4; r++)
                    acc[r] = __hfma2(zr[4 * k + r], pk, acc[r]);
            }
        }
        *(uint4*)pA = *(uint4*)accA;
        *(uint4*)pB = *(uint4*)accB;
        __syncthreads();

        // ---- epilogue: warp f<8 combines 16 warp-partials (fp32), +x, norm|store ----
        if (w < 8) {
            int d0 = lane * 2;
            float2 v = *(const float2*)(xs + w * XSTR + d0);
            #pragma unroll
            for (int gg = 0; gg < 16; gg++) {
                __half2 hv = *(const __half2*)(part + gg * PWS + w * PFS + d0);
                float2 fv = __half22float2(hv);
                v.x += fv.x; v.y += fv.y;
            }
            if (it < 2) {
                float s2 = v.x * v.x + v.y * v.y;
                #pragma unroll
                for (int o = 16; o; o >>= 1) s2 += __shfl_xor_sync(0xffffffffu, s2, o);
                float r = rsqrtf(fmaxf(s2, 1e-24f));
                *(__half2*)(us + w * UH + d0) = __floats2half2_rn(v.x * r, v.y * r);
            } else {
                *(float2*)(out + (size_t)b * 512 + w * 64 + d0) = v;
            }
        }
        if (it < 2) __syncthreads();
    }
}

extern "C" void kernel_launch(void* const* d_in, const int* in_sizes, int n_in,
                              void* d_out, int out_size)
{
    const float* feat = (const float*)d_in[0];   // [2048, 512]
    const float* meta = (const float*)d_in[1];   // [2048, 64, 512]
    float* out = (float*)d_out;

    const int B = in_sizes[0] / 512;             // 2048
    const size_t smem_bytes = (size_t)SMEM_FLOATS * sizeof(float);

    cudaFuncSetAttribute(hete_attention_kernel,
                         cudaFuncAttributeMaxDynamicSharedMemorySize,
                         (int)smem_bytes);

    hete_attention_kernel<<<B, NTHREADS, smem_bytes>>>(feat, meta, out);
}